// round 2
// baseline (speedup 1.0000x reference)
#include <cuda_runtime.h>

#define T_STEPS 512
#define BATCH   512
#define SDIM    64
#define HID     128
#define ADIM    10

#define NCTA    128
#define NTHR    512
#define CLUSTER 8
#define BPC     32
#define KA      192   // layer0: k 0..127 = h0 (W_hh0), 128..191 = x (W_ih0)
#define KB      256   // layer1: k 0..127 = h0 (W_ih1), 128..255 = h1 (W_hh1)

// smem float offsets
#define SZ_WA   (16*2*KA*2)        // 12288
#define SZ_WB   (16*2*KB*2)        // 16384
#define SZ_WO   (HID*ADIM)         // 1280
#define OFF_WA  0
#define OFF_WB  (OFF_WA + SZ_WA)   // 12288
#define OFF_WO  (OFF_WB + SZ_WB)   // 28672
#define OFF_IN  29968              // 16B aligned
#define SZ_IN   (320*32*2)         // 20480
#define SMEM_BYTES ((OFF_IN + SZ_IN)*4)  // 201792

typedef unsigned long long u64;

// ping-pong hidden state, [j][b] layout
__device__ float g_h0[2][HID*BATCH];
__device__ float g_h1[2][HID*BATCH];

__device__ __forceinline__ float tanh_fast(float v) {
    float r; asm("tanh.approx.f32 %0, %1;" : "=f"(r) : "f"(v)); return r;
}
__device__ __forceinline__ float sigmoid_fast(float v) {
    return 0.5f * tanh_fast(0.5f * v) + 0.5f;
}
__device__ __forceinline__ u64 ffma2(u64 a, u64 b, u64 c) {
    u64 d; asm("fma.rn.f32x2 %0, %1, %2, %3;" : "=l"(d) : "l"(a), "l"(b), "l"(c)); return d;
}
__device__ __forceinline__ u64 pack2(float lo, float hi) {
    u64 d; asm("mov.b64 %0, {%1, %2};" : "=l"(d) : "f"(lo), "f"(hi)); return d;
}
__device__ __forceinline__ void unpack2(u64 v, float& lo, float& hi) {
    asm("mov.b64 {%0, %1}, %2;" : "=f"(lo), "=f"(hi) : "l"(v));
}
__device__ __forceinline__ void cluster_bar() {
    asm volatile("barrier.cluster.arrive.aligned;" ::: "memory");
    asm volatile("barrier.cluster.wait.aligned;"   ::: "memory");
}

// K-range GEMM: weights pre-interleaved as (g_lo[k],g_hi[k]) pairs, x duplicated f32x2.
template <int N>
__device__ __forceinline__ void gemm2(const float* __restrict__ wif,
                                      const float* __restrict__ wgo,
                                      const float* __restrict__ sx, int b2,
                                      u64& aif, u64& ago)
{
    #pragma unroll 4
    for (int k = 0; k < N; k += 2) {
        ulonglong2 w0 = *(const ulonglong2*)(wif + 2*k);
        ulonglong2 w1 = *(const ulonglong2*)(wgo + 2*k);
        u64 x0 = *(const u64*)(sx + k*64 + b2);
        u64 x1 = *(const u64*)(sx + (k+1)*64 + b2);
        aif = ffma2(w0.x, x0, aif);
        ago = ffma2(w1.x, x0, ago);
        aif = ffma2(w0.y, x1, aif);
        ago = ffma2(w1.y, x1, ago);
    }
}

__device__ __forceinline__ float lstm_epi(u64 aif, u64 ago, float& c) {
    float ai, af, ag, ao;
    unpack2(aif, ai, af);
    unpack2(ago, ag, ao);
    float iG = sigmoid_fast(ai), fG = sigmoid_fast(af);
    float gG = tanh_fast(ag),    oG = sigmoid_fast(ao);
    c = fG * c + iG * gG;
    return oG * tanh_fast(c);
}

__global__ void __cluster_dims__(CLUSTER, 1, 1) __launch_bounds__(NTHR, 1)
lstm_cluster(const float* __restrict__ x,
             const float* __restrict__ W_ih0, const float* __restrict__ W_hh0,
             const float* __restrict__ b_ih0, const float* __restrict__ b_hh0,
             const float* __restrict__ W_ih1, const float* __restrict__ W_hh1,
             const float* __restrict__ b_ih1, const float* __restrict__ b_hh1,
             const float* __restrict__ W_out, const float* __restrict__ b_out,
             float* __restrict__ out)
{
    extern __shared__ float smem[];
    float* sWA = smem + OFF_WA;
    float* sWB = smem + OFF_WB;
    float* sWO = smem + OFF_WO;
    float* sIn = smem + OFF_IN;    // [k][b][2] duplicated f32x2, k<320

    const int tid = threadIdx.x;
    const int bid = blockIdx.x;
    const int hs  = bid & (CLUSTER - 1);   // hidden slice (cluster rank)
    const int bs  = bid >> 3;              // batch slice (cluster id)
    const int j0  = hs * 16;
    const int b0  = bs * BPC;
    const int b   = tid & 31;              // lane = batch
    const int wid = tid >> 5;              // warp = hidden unit (16 warps)
    const int jg  = j0 + wid;              // global hidden index
    const int b2  = 2 * b;

    // ---- weights to smem: sWA[((j*2+gp)*KA + k)*2 + p], gate = gp*2+p (i,f,g,o) ----
    for (int idx = tid; idx < SZ_WA; idx += NTHR) {
        int p = idx & 1, r = idx >> 1;
        int k = r % KA; int r2 = r / KA;
        int gp = r2 & 1; int j = r2 >> 1;
        int row = (gp*2 + p) * HID + j0 + j;
        sWA[idx] = (k < HID) ? W_hh0[row*HID + k] : W_ih0[row*SDIM + (k - HID)];
    }
    for (int idx = tid; idx < SZ_WB; idx += NTHR) {
        int p = idx & 1, r = idx >> 1;
        int k = r % KB; int r2 = r / KB;
        int gp = r2 & 1; int j = r2 >> 1;
        int row = (gp*2 + p) * HID + j0 + j;
        sWB[idx] = (k < HID) ? W_ih1[row*HID + k] : W_hh1[row*HID + (k - HID)];
    }
    for (int idx = tid; idx < SZ_WO; idx += NTHR) {
        int j = idx / ADIM, a = idx - j*ADIM;
        sWO[idx] = W_out[a*HID + j];       // transposed [j][a]
    }

    // ---- packed biases ----
    u64 bA_if = pack2(b_ih0[0*HID+jg] + b_hh0[0*HID+jg], b_ih0[1*HID+jg] + b_hh0[1*HID+jg]);
    u64 bA_go = pack2(b_ih0[2*HID+jg] + b_hh0[2*HID+jg], b_ih0[3*HID+jg] + b_hh0[3*HID+jg]);
    u64 bB_if = pack2(b_ih1[0*HID+jg] + b_hh1[0*HID+jg], b_ih1[1*HID+jg] + b_hh1[1*HID+jg]);
    u64 bB_go = pack2(b_ih1[2*HID+jg] + b_hh1[2*HID+jg], b_ih1[3*HID+jg] + b_hh1[3*HID+jg]);

    // head constants (threads 0..39)
    const int lb = tid / ADIM;
    const int ha = tid - lb * ADIM;
    const int hbb = hs * 4 + lb;           // column within CTA's batch slice
    float bout_r = (tid < 4*ADIM) ? b_out[ha] : 0.0f;

    // per-warp weight bases
    const float* wifA = sWA + wid * (2*KA*2);
    const float* wgoA = wifA + KA*2;
    const float* wifB = sWB + wid * (2*KB*2);
    const float* wgoB = wifB + KB*2;

    // ---- zero h1(-1) (slot 1): this CTA's [j0..j0+16) x [b0..b0+32) tile ----
    g_h1[1][(j0 + (tid >> 5)) * BATCH + b0 + (tid & 31)] = 0.0f;

    // ---- prologue: L0(0) ----
    #pragma unroll
    for (int i = 0; i < 8; ++i) {          // region0 = h0(-1) = 0
        int idx = tid + i*NTHR; int bb = idx & 31; int k = idx >> 5;
        *(float2*)&sIn[(k*32 + bb)*2] = make_float2(0.f, 0.f);
    }
    #pragma unroll
    for (int i = 0; i < 4; ++i) {          // region2 = x(0)
        int idx = tid + i*NTHR; int kx = idx & 63; int bb = idx >> 6;
        float v = x[((size_t)0*BATCH + b0 + bb)*SDIM + kx];
        *(float2*)&sIn[((256 + kx)*32 + bb)*2] = make_float2(v, v);
    }
    __syncthreads();

    float c0 = 0.f, c1 = 0.f;
    {
        u64 aif = bA_if, ago = bA_go;
        gemm2<128>(wifA, wgoA, sIn, b2, aif, ago);
        gemm2<64>(wifA + 256, wgoA + 256, sIn + 256*64, b2, aif, ago);
        g_h0[0][jg*BATCH + b0 + b] = lstm_epi(aif, ago, c0);
    }
    __threadfence();
    cluster_bar();

    // ---- main loop: per block = [stage; head(t-1); L1(t); L0(t+1); bar] ----
    for (int t = 0; t < T_STEPS; ++t) {
        const int sc = t & 1;
        const float* h0src = g_h0[sc];         // h0(t)
        const float* h1src = g_h1[sc ^ 1];     // h1(t-1)

        #pragma unroll
        for (int i = 0; i < 8; ++i) {          // region0 = h0(t)
            int idx = tid + i*NTHR; int bb = idx & 31; int k = idx >> 5;
            float v = __ldcg(&h0src[k*BATCH + b0 + bb]);
            *(float2*)&sIn[(k*32 + bb)*2] = make_float2(v, v);
        }
        #pragma unroll
        for (int i = 0; i < 8; ++i) {          // region1 = h1(t-1)
            int idx = tid + i*NTHR; int bb = idx & 31; int k = idx >> 5;
            float v = __ldcg(&h1src[k*BATCH + b0 + bb]);
            *(float2*)&sIn[((128 + k)*32 + bb)*2] = make_float2(v, v);
        }
        if (t < T_STEPS - 1) {
            #pragma unroll
            for (int i = 0; i < 4; ++i) {      // region2 = x(t+1)
                int idx = tid + i*NTHR; int kx = idx & 63; int bb = idx >> 6;
                float v = x[((size_t)(t+1)*BATCH + b0 + bb)*SDIM + kx];
                *(float2*)&sIn[((256 + kx)*32 + bb)*2] = make_float2(v, v);
            }
        }
        __syncthreads();

        // output head for step t-1 (reads region1 = h1(t-1) from smem)
        if (t > 0 && tid < 4*ADIM) {
            float s = bout_r;
            #pragma unroll 8
            for (int j = 0; j < HID; ++j)
                s = fmaf(sIn[((128 + j)*32 + hbb)*2], sWO[j*ADIM + ha], s);
            out[((size_t)(t-1)*BATCH + b0 + hbb)*ADIM + ha] = tanh_fast(s);
        }

        // L1(t): K = [h0(t) | h1(t-1)] = sIn[0..256)
        {
            u64 aif = bB_if, ago = bB_go;
            gemm2<256>(wifB, wgoB, sIn, b2, aif, ago);
            g_h1[sc][jg*BATCH + b0 + b] = lstm_epi(aif, ago, c1);
        }

        // L0(t+1): K = [h0(t) (region0) | x(t+1) (region2)]
        if (t < T_STEPS - 1) {
            u64 aif = bA_if, ago = bA_go;
            gemm2<128>(wifA, wgoA, sIn, b2, aif, ago);
            gemm2<64>(wifA + 256, wgoA + 256, sIn + 256*64, b2, aif, ago);
            g_h0[sc ^ 1][jg*BATCH + b0 + b] = lstm_epi(aif, ago, c0);
        }

        __threadfence();
        cluster_bar();
    }

    // ---- final head: t = T-1, h1(511) in slot 1 (global reads) ----
    if (tid < 4*ADIM) {
        float s = bout_r;
        const float* hp = &g_h1[1][b0 + hbb];
        #pragma unroll 8
        for (int j = 0; j < HID; ++j)
            s = fmaf(__ldcg(&hp[j*BATCH]), sWO[j*ADIM + ha], s);
        out[((size_t)(T_STEPS-1)*BATCH + b0 + hbb)*ADIM + ha] = tanh_fast(s);
    }
}

extern "C" void kernel_launch(void* const* d_in, const int* in_sizes, int n_in,
                              void* d_out, int out_size)
{
    const float* x    = (const float*)d_in[0];
    const float* Wih0 = (const float*)d_in[1];
    const float* Whh0 = (const float*)d_in[2];
    const float* bih0 = (const float*)d_in[3];
    const float* bhh0 = (const float*)d_in[4];
    const float* Wih1 = (const float*)d_in[5];
    const float* Whh1 = (const float*)d_in[6];
    const float* bih1 = (const float*)d_in[7];
    const float* bhh1 = (const float*)d_in[8];
    const float* Wout = (const float*)d_in[9];
    const float* bout = (const float*)d_in[10];
    float* out = (float*)d_out;

    cudaFuncSetAttribute(lstm_cluster,
                         cudaFuncAttributeMaxDynamicSharedMemorySize, SMEM_BYTES);

    lstm_cluster<<<NCTA, NTHR, SMEM_BYTES>>>(
        x, Wih0, Whh0, bih0, bhh0, Wih1, Whh1, bih1, bhh1, Wout, bout, out);
}